// round 5
// baseline (speedup 1.0000x reference)
#include <cuda_runtime.h>
#include <cstdint>

typedef unsigned long long u64;

#define BB 4096
#define TT 200
#define H1 55
#define H2 30
#define NTHR 224
#define EPC 28
#define GRID 147

// ---- dynamic smem byte offsets ----
#define OFF_W1  0                    // float4[72][56]  (rows: 16 x-k then 56 h1-k)
#define OFF_W2  64512                // float4[86][32]  (rows: 56 h1-k then 30 h2-k)
#define OFF_B1  108544               // float4[56]
#define OFF_B2  109440               // float4[32]
#define OFF_XS  109952               // u64[2][16][40]  splatted x strip
#define OFF_H1S 120192               // u64[2][56][40]  splatted h1 strip
#define OFF_H1F 156032               // float[2][56][28] h1 float strip (layer2 input)
#define OFF_H2F 168576               // float[2][30][28] h2 float strip
#define SMEM_BYTES 175296

#define XROW 40
#define HROW 40

static __device__ __forceinline__ u64 pk2(float lo, float hi) {
    u64 r; asm("mov.b64 %0, {%1, %2};" : "=l"(r) : "f"(lo), "f"(hi)); return r;
}
static __device__ __forceinline__ void unpk(u64 v, float& lo, float& hi) {
    asm("mov.b64 {%0, %1}, %2;" : "=f"(lo), "=f"(hi) : "l"(v));
}
static __device__ __forceinline__ void fma2(u64& acc, u64 a, u64 b) {
    asm("fma.rn.f32x2 %0, %1, %2, %0;" : "+l"(acc) : "l"(a), "l"(b));
}
static __device__ __forceinline__ float sigf(float v) {
    return __fdividef(1.0f, 1.0f + __expf(-v));
}
static __device__ __forceinline__ float tanhf_fast(float v) {
    return __fdividef(2.0f, 1.0f + __expf(-2.0f * v)) - 1.0f;
}

// 14 packed FMAs against 7 splatted h values (slots s..s+6 of a 40-u64 row)
#define L1K(WPTR, HPTR) do { \
    const ulonglong2 wv_ = *(const ulonglong2*)(WPTR); \
    const ulonglong2 q0_ = *(const ulonglong2*)((HPTR) + 0); \
    const ulonglong2 q1_ = *(const ulonglong2*)((HPTR) + 2); \
    const ulonglong2 q2_ = *(const ulonglong2*)((HPTR) + 4); \
    const u64 q3_ = (HPTR)[6]; \
    fma2(aif[0], wv_.x, q0_.x); fma2(ago[0], wv_.y, q0_.x); \
    fma2(aif[1], wv_.x, q0_.y); fma2(ago[1], wv_.y, q0_.y); \
    fma2(aif[2], wv_.x, q1_.x); fma2(ago[2], wv_.y, q1_.x); \
    fma2(aif[3], wv_.x, q1_.y); fma2(ago[3], wv_.y, q1_.y); \
    fma2(aif[4], wv_.x, q2_.x); fma2(ago[4], wv_.y, q2_.x); \
    fma2(aif[5], wv_.x, q2_.y); fma2(ago[5], wv_.y, q2_.y); \
    fma2(aif[6], wv_.x, q3_);   fma2(ago[6], wv_.y, q3_); } while (0)

#define L2K(WPTR, HPTR) do { \
    const ulonglong2 wv_ = *(const ulonglong2*)(WPTR); \
    const float4 hv_ = *(const float4*)(HPTR); \
    const u64 s0_ = pk2(hv_.x, hv_.x), s1_ = pk2(hv_.y, hv_.y); \
    const u64 s2_ = pk2(hv_.z, hv_.z), s3_ = pk2(hv_.w, hv_.w); \
    fma2(a2if[0], wv_.x, s0_); fma2(a2go[0], wv_.y, s0_); \
    fma2(a2if[1], wv_.x, s1_); fma2(a2go[1], wv_.y, s1_); \
    fma2(a2if[2], wv_.x, s2_); fma2(a2go[2], wv_.y, s2_); \
    fma2(a2if[3], wv_.x, s3_); fma2(a2go[3], wv_.y, s3_); } while (0)

__global__ void __launch_bounds__(NTHR, 1)
lstm2_kernel(const float* __restrict__ x,
             const float* __restrict__ Wih1, const float* __restrict__ Whh1,
             const float* __restrict__ bih1, const float* __restrict__ bhh1,
             const float* __restrict__ Wih2, const float* __restrict__ Whh2,
             const float* __restrict__ bih2, const float* __restrict__ bhh2,
             const float* __restrict__ Wfc,  const float* __restrict__ bfc,
             float* __restrict__ out)
{
    extern __shared__ char sm[];
    float4* W1  = (float4*)(sm + OFF_W1);
    float4* W2  = (float4*)(sm + OFF_W2);
    float4* B1  = (float4*)(sm + OFF_B1);
    float4* B2  = (float4*)(sm + OFF_B2);
    u64*    XS  = (u64*)(sm + OFF_XS);
    u64*    H1S = (u64*)(sm + OFF_H1S);
    float*  H1F = (float*)(sm + OFF_H1F);
    float*  H2F = (float*)(sm + OFF_H2F);

    const int tid = threadIdx.x;
    const int ebase = blockIdx.x * EPC;

    // ---------------- stage weights ----------------
    // W1 rows 0..15 = Wih1 (k over 16 features), rows 16..71 = Whh1 (k over 56 h-slots)
    for (int i = tid; i < 72 * 56; i += NTHR) {
        int k = i / 56, u = i % 56;
        float4 v = make_float4(0.f, 0.f, 0.f, 0.f);
        if (u < H1) {
            if (k < 16) {
                v.x = Wih1[(0 * H1 + u) * 16 + k];
                v.y = Wih1[(1 * H1 + u) * 16 + k];
                v.z = Wih1[(2 * H1 + u) * 16 + k];
                v.w = Wih1[(3 * H1 + u) * 16 + k];
            } else if (k - 16 < H1) {
                int j = k - 16;
                v.x = Whh1[(0 * H1 + u) * H1 + j];
                v.y = Whh1[(1 * H1 + u) * H1 + j];
                v.z = Whh1[(2 * H1 + u) * H1 + j];
                v.w = Whh1[(3 * H1 + u) * H1 + j];
            }
        }
        W1[i] = v;
    }
    // W2 rows 0..55 = Wih2 (k over 56 h1-slots), rows 56..85 = Whh2 (k over 30 h2)
    for (int i = tid; i < 86 * 32; i += NTHR) {
        int k = i / 32, u = i % 32;
        float4 v = make_float4(0.f, 0.f, 0.f, 0.f);
        if (u < H2) {
            if (k < 56) {
                if (k < H1) {
                    v.x = Wih2[(0 * H2 + u) * H1 + k];
                    v.y = Wih2[(1 * H2 + u) * H1 + k];
                    v.z = Wih2[(2 * H2 + u) * H1 + k];
                    v.w = Wih2[(3 * H2 + u) * H1 + k];
                }
            } else {
                int j = k - 56;
                v.x = Whh2[(0 * H2 + u) * H2 + j];
                v.y = Whh2[(1 * H2 + u) * H2 + j];
                v.z = Whh2[(2 * H2 + u) * H2 + j];
                v.w = Whh2[(3 * H2 + u) * H2 + j];
            }
        }
        W2[i] = v;
    }
    for (int u = tid; u < 56; u += NTHR) {
        float4 v = make_float4(0.f, 0.f, 0.f, 0.f);
        if (u < H1) {
            v.x = bih1[0 * H1 + u] + bhh1[0 * H1 + u];
            v.y = bih1[1 * H1 + u] + bhh1[1 * H1 + u];
            v.z = bih1[2 * H1 + u] + bhh1[2 * H1 + u];
            v.w = bih1[3 * H1 + u] + bhh1[3 * H1 + u];
        }
        B1[u] = v;
    }
    for (int u = tid; u < 32; u += NTHR) {
        float4 v = make_float4(0.f, 0.f, 0.f, 0.f);
        if (u < H2) {
            v.x = bih2[0 * H2 + u] + bhh2[0 * H2 + u];
            v.y = bih2[1 * H2 + u] + bhh2[1 * H2 + u];
            v.z = bih2[2 * H2 + u] + bhh2[2 * H2 + u];
            v.w = bih2[3 * H2 + u] + bhh2[3 * H2 + u];
        }
        B2[u] = v;
    }
    // zero h1s buf1, h2f buf1 (the t = -1 state)
    for (int i = tid; i < 56 * HROW; i += NTHR) H1S[56 * HROW + i] = 0ull;
    for (int i = tid; i < 30 * 28; i += NTHR)  H2F[30 * 28 + i] = 0.f;

    // stage x(t=0) into XS buf 0
    if (tid < 112) {
        int e = tid >> 2, q = tid & 3;
        int eg = ebase + e;
        float4 v = make_float4(0.f, 0.f, 0.f, 0.f);
        if (eg < BB) v = __ldg((const float4*)(x + ((size_t)eg * TT) * 16) + q);
        int slot = 10 * (e / 7) + (e % 7);
        u64* xd = XS + 0;
        xd[(4 * q + 0) * XROW + slot] = pk2(v.x, v.x);
        xd[(4 * q + 1) * XROW + slot] = pk2(v.y, v.y);
        xd[(4 * q + 2) * XROW + slot] = pk2(v.z, v.z);
        xd[(4 * q + 3) * XROW + slot] = pk2(v.w, v.w);
    }
    __syncthreads();

    // ---------------- per-thread roles ----------------
    const int u1 = tid >> 2;          // layer1 quad 0..55
    const int g1 = tid & 3;           // layer1 group (7 elems)
    const int s1 = 10 * g1;           // slot base in 40-u64 rows
    const int u2 = tid / 7;           // layer2 quad 0..31 (30,31 = pad)
    const int g2 = tid % 7;           // layer2 group (4 elems)

    const ulonglong2 b1v = *(const ulonglong2*)(B1 + u1);
    const ulonglong2 b2v = *(const ulonglong2*)(B2 + u2);

    float c1[7], c2[4];
#pragma unroll
    for (int j = 0; j < 7; ++j) c1[j] = 0.f;
#pragma unroll
    for (int j = 0; j < 4; ++j) c2[j] = 0.f;

    for (int t = 0; t < TT; ++t) {
        const int cur = t & 1, nxt = cur ^ 1;

        // prefetch x(t+1) to regs (LDG latency hidden behind layer1)
        float4 xv = make_float4(0.f, 0.f, 0.f, 0.f);
        const bool xload = (tid < 112) && (t + 1 < TT);
        if (xload) {
            int e = tid >> 2, q = tid & 3;
            int eg = ebase + e;
            if (eg < BB)
                xv = __ldg((const float4*)(x + ((size_t)eg * TT + t + 1) * 16) + q);
        }

        // ---------------- layer 1 ----------------
        u64 aif[7], ago[7];
#pragma unroll
        for (int j = 0; j < 7; ++j) { aif[j] = b1v.x; ago[j] = b1v.y; }

        {
            const float4* wr = W1 + u1;
            const u64* hr = XS + cur * 16 * XROW + s1;
#pragma unroll 4
            for (int k = 0; k < 16; ++k) {
                L1K(wr, hr);
                wr += 56; hr += XROW;
            }
            hr = H1S + nxt * 56 * HROW + s1;   // h1(t-1)
#pragma unroll 4
            for (int k = 0; k < 56; ++k) {
                L1K(wr, hr);
                wr += 56; hr += HROW;
            }
        }

        {
            u64* hs = H1S + cur * 56 * HROW + u1 * HROW + s1;
            float* hf = H1F + cur * 56 * 28 + u1 * 28 + 7 * g1;
#pragma unroll
            for (int j = 0; j < 7; ++j) {
                float iv, fv, gv, ov;
                unpk(aif[j], iv, fv); unpk(ago[j], gv, ov);
                iv = sigf(iv); fv = sigf(fv);
                gv = tanhf_fast(gv); ov = sigf(ov);
                c1[j] = fv * c1[j] + iv * gv;
                const float h = ov * tanhf_fast(c1[j]);
                hs[j] = pk2(h, h);
                hf[j] = h;
            }
        }
        __syncthreads();   // h1(t) visible CTA-wide

        // stage x(t+1) into XS[nxt]
        if (xload) {
            int e = tid >> 2, q = tid & 3;
            int slot = 10 * (e / 7) + (e % 7);
            u64* xd = XS + nxt * 16 * XROW;
            xd[(4 * q + 0) * XROW + slot] = pk2(xv.x, xv.x);
            xd[(4 * q + 1) * XROW + slot] = pk2(xv.y, xv.y);
            xd[(4 * q + 2) * XROW + slot] = pk2(xv.z, xv.z);
            xd[(4 * q + 3) * XROW + slot] = pk2(xv.w, xv.w);
        }

        // ---------------- layer 2 ----------------
        u64 a2if[4], a2go[4];
#pragma unroll
        for (int j = 0; j < 4; ++j) { a2if[j] = b2v.x; a2go[j] = b2v.y; }

        {
            const float4* wr = W2 + u2;
            const float* hf = H1F + cur * 56 * 28 + 4 * g2;
#pragma unroll 4
            for (int k = 0; k < 56; ++k) {
                L2K(wr, hf);
                wr += 32; hf += 28;
            }
            hf = H2F + nxt * 30 * 28 + 4 * g2;   // h2(t-1)
#pragma unroll 4
            for (int k = 0; k < 30; ++k) {
                L2K(wr, hf);
                wr += 32; hf += 28;
            }
        }

        {
            float h2o[4];
#pragma unroll
            for (int j = 0; j < 4; ++j) {
                float iv, fv, gv, ov;
                unpk(a2if[j], iv, fv); unpk(a2go[j], gv, ov);
                iv = sigf(iv); fv = sigf(fv);
                gv = tanhf_fast(gv); ov = sigf(ov);
                c2[j] = fv * c2[j] + iv * gv;
                h2o[j] = ov * tanhf_fast(c2[j]);
            }
            if (u2 < H2) {
                float4* dst = (float4*)(H2F + cur * 30 * 28 + u2 * 28 + 4 * g2);
                *dst = make_float4(h2o[0], h2o[1], h2o[2], h2o[3]);
            }
        }
        __syncthreads();   // h2(t), x(t+1) visible; safe to reuse buffers
    }

    // ---------------- final FC ----------------
    // h2(199) is in H2F buffer (199 & 1) = 1
    if (tid < EPC * 6) {
        const int e = tid / 6, m = tid % 6;
        const int eg = ebase + e;
        if (eg < BB) {
            const float* h2 = H2F + 1 * 30 * 28;
            float s = bfc[m];
#pragma unroll
            for (int u = 0; u < H2; ++u)
                s += Wfc[m * H2 + u] * h2[u * 28 + e];
            out[(size_t)eg * 6 + m] = s;
        }
    }
}

extern "C" void kernel_launch(void* const* d_in, const int* in_sizes, int n_in,
                              void* d_out, int out_size) {
    (void)in_sizes; (void)n_in; (void)out_size;
    const float* x    = (const float*)d_in[0];
    const float* Wih1 = (const float*)d_in[1];
    const float* Whh1 = (const float*)d_in[2];
    const float* bih1 = (const float*)d_in[3];
    const float* bhh1 = (const float*)d_in[4];
    const float* Wih2 = (const float*)d_in[5];
    const float* Whh2 = (const float*)d_in[6];
    const float* bih2 = (const float*)d_in[7];
    const float* bhh2 = (const float*)d_in[8];
    const float* Wfc  = (const float*)d_in[9];
    const float* bfc  = (const float*)d_in[10];
    float* out = (float*)d_out;

    static bool attr_set = false;
    if (!attr_set) {
        cudaFuncSetAttribute(lstm2_kernel,
                             cudaFuncAttributeMaxDynamicSharedMemorySize, SMEM_BYTES);
        attr_set = true;
    }
    lstm2_kernel<<<GRID, NTHR, SMEM_BYTES>>>(x, Wih1, Whh1, bih1, bhh1,
                                             Wih2, Whh2, bih2, bhh2, Wfc, bfc, out);
}

// round 6
// speedup vs baseline: 1.1227x; 1.1227x over previous
#include <cuda_runtime.h>
#include <cstdint>

typedef unsigned long long u64;

#define BB 4096
#define TT 200
#define H1 55
#define H2 30
#define NTHR 224
#define EPC 28
#define GRID 147

// ---- dynamic smem byte offsets ----
#define OFF_W1  0                    // float4[72][56]  rows: 16 x-k then 56 h1-k
#define OFF_W2  64512                // float4[86][32]  rows: 56 h1-k then 30 h2-k
#define OFF_B1  108544               // float4[56]
#define OFF_B2  109440               // float4[32]
#define OFF_XS  109952               // float[2][16][32]   x strip (8-slot groups)
#define OFF_H1A 114048               // float[2][56][32]   h1 strip, layer1 view
#define OFF_H1B 128384               // float[2][56][28]   h1 strip, layer2 view
#define OFF_H2  140928               // float[2][30][28]   h2 strip
#define SMEM_BYTES 147648

static __device__ __forceinline__ u64 pk2(float lo, float hi) {
    u64 r; asm("mov.b64 %0, {%1, %2};" : "=l"(r) : "f"(lo), "f"(hi)); return r;
}
static __device__ __forceinline__ void unpk(u64 v, float& lo, float& hi) {
    asm("mov.b64 {%0, %1}, %2;" : "=f"(lo), "=f"(hi) : "l"(v));
}
static __device__ __forceinline__ void fma2(u64& acc, u64 a, u64 b) {
    asm("fma.rn.f32x2 %0, %1, %2, %0;" : "+l"(acc) : "l"(a), "l"(b));
}
static __device__ __forceinline__ float sigf(float v) {
    return __fdividef(1.0f, 1.0f + __expf(-v));
}
static __device__ __forceinline__ float tanhf_fast(float v) {
    return __fdividef(2.0f, 1.0f + __expf(-2.0f * v)) - 1.0f;
}

// layer1 k-iter: weight pair (if,go) vs 7 h values from an 8-float slot group
#define L1K(WPTR, HPTR) do { \
    const ulonglong2 wv_ = *(const ulonglong2*)(WPTR); \
    const float4 q0_ = *(const float4*)(HPTR); \
    const float4 q1_ = *(const float4*)((HPTR) + 4); \
    u64 s_; \
    s_ = pk2(q0_.x, q0_.x); fma2(aif[0], wv_.x, s_); fma2(ago[0], wv_.y, s_); \
    s_ = pk2(q0_.y, q0_.y); fma2(aif[1], wv_.x, s_); fma2(ago[1], wv_.y, s_); \
    s_ = pk2(q0_.z, q0_.z); fma2(aif[2], wv_.x, s_); fma2(ago[2], wv_.y, s_); \
    s_ = pk2(q0_.w, q0_.w); fma2(aif[3], wv_.x, s_); fma2(ago[3], wv_.y, s_); \
    s_ = pk2(q1_.x, q1_.x); fma2(aif[4], wv_.x, s_); fma2(ago[4], wv_.y, s_); \
    s_ = pk2(q1_.y, q1_.y); fma2(aif[5], wv_.x, s_); fma2(ago[5], wv_.y, s_); \
    s_ = pk2(q1_.z, q1_.z); fma2(aif[6], wv_.x, s_); fma2(ago[6], wv_.y, s_); } while (0)

// layer2 k-iter: weight pair vs 4 h values
#define L2K(WPTR, HPTR) do { \
    const ulonglong2 wv_ = *(const ulonglong2*)(WPTR); \
    const float4 hv_ = *(const float4*)(HPTR); \
    u64 s_; \
    s_ = pk2(hv_.x, hv_.x); fma2(a2if[0], wv_.x, s_); fma2(a2go[0], wv_.y, s_); \
    s_ = pk2(hv_.y, hv_.y); fma2(a2if[1], wv_.x, s_); fma2(a2go[1], wv_.y, s_); \
    s_ = pk2(hv_.z, hv_.z); fma2(a2if[2], wv_.x, s_); fma2(a2go[2], wv_.y, s_); \
    s_ = pk2(hv_.w, hv_.w); fma2(a2if[3], wv_.x, s_); fma2(a2go[3], wv_.y, s_); } while (0)

__global__ void __launch_bounds__(NTHR, 1)
lstm2_kernel(const float* __restrict__ x,
             const float* __restrict__ Wih1, const float* __restrict__ Whh1,
             const float* __restrict__ bih1, const float* __restrict__ bhh1,
             const float* __restrict__ Wih2, const float* __restrict__ Whh2,
             const float* __restrict__ bih2, const float* __restrict__ bhh2,
             const float* __restrict__ Wfc,  const float* __restrict__ bfc,
             float* __restrict__ out)
{
    extern __shared__ char sm[];
    float4* W1  = (float4*)(sm + OFF_W1);
    float4* W2  = (float4*)(sm + OFF_W2);
    float4* B1  = (float4*)(sm + OFF_B1);
    float4* B2  = (float4*)(sm + OFF_B2);
    float*  XS  = (float*)(sm + OFF_XS);
    float*  H1A = (float*)(sm + OFF_H1A);
    float*  H1B = (float*)(sm + OFF_H1B);
    float*  H2F = (float*)(sm + OFF_H2);

    const int tid = threadIdx.x;
    const int ebase = blockIdx.x * EPC;

    // ---------------- stage weights ----------------
    for (int i = tid; i < 72 * 56; i += NTHR) {
        int k = i / 56, u = i % 56;
        float4 v = make_float4(0.f, 0.f, 0.f, 0.f);
        if (u < H1) {
            if (k < 16) {
                v.x = Wih1[(0 * H1 + u) * 16 + k];
                v.y = Wih1[(1 * H1 + u) * 16 + k];
                v.z = Wih1[(2 * H1 + u) * 16 + k];
                v.w = Wih1[(3 * H1 + u) * 16 + k];
            } else if (k - 16 < H1) {
                int j = k - 16;
                v.x = Whh1[(0 * H1 + u) * H1 + j];
                v.y = Whh1[(1 * H1 + u) * H1 + j];
                v.z = Whh1[(2 * H1 + u) * H1 + j];
                v.w = Whh1[(3 * H1 + u) * H1 + j];
            }
        }
        W1[i] = v;
    }
    for (int i = tid; i < 86 * 32; i += NTHR) {
        int k = i / 32, u = i % 32;
        float4 v = make_float4(0.f, 0.f, 0.f, 0.f);
        if (u < H2) {
            if (k < 56) {
                if (k < H1) {
                    v.x = Wih2[(0 * H2 + u) * H1 + k];
                    v.y = Wih2[(1 * H2 + u) * H1 + k];
                    v.z = Wih2[(2 * H2 + u) * H1 + k];
                    v.w = Wih2[(3 * H2 + u) * H1 + k];
                }
            } else {
                int j = k - 56;
                v.x = Whh2[(0 * H2 + u) * H2 + j];
                v.y = Whh2[(1 * H2 + u) * H2 + j];
                v.z = Whh2[(2 * H2 + u) * H2 + j];
                v.w = Whh2[(3 * H2 + u) * H2 + j];
            }
        }
        W2[i] = v;
    }
    for (int u = tid; u < 56; u += NTHR) {
        float4 v = make_float4(0.f, 0.f, 0.f, 0.f);
        if (u < H1) {
            v.x = bih1[0 * H1 + u] + bhh1[0 * H1 + u];
            v.y = bih1[1 * H1 + u] + bhh1[1 * H1 + u];
            v.z = bih1[2 * H1 + u] + bhh1[2 * H1 + u];
            v.w = bih1[3 * H1 + u] + bhh1[3 * H1 + u];
        }
        B1[u] = v;
    }
    for (int u = tid; u < 32; u += NTHR) {
        float4 v = make_float4(0.f, 0.f, 0.f, 0.f);
        if (u < H2) {
            v.x = bih2[0 * H2 + u] + bhh2[0 * H2 + u];
            v.y = bih2[1 * H2 + u] + bhh2[1 * H2 + u];
            v.z = bih2[2 * H2 + u] + bhh2[2 * H2 + u];
            v.w = bih2[3 * H2 + u] + bhh2[3 * H2 + u];
        }
        B2[u] = v;
    }
    // zero all state strips (both buffers)
    for (int i = tid; i < (SMEM_BYTES - OFF_XS) / 4; i += NTHR)
        XS[i] = 0.f;
    __syncthreads();

    // stage x(t=0) into XS buf 0
    if (tid < 112) {
        int e = tid >> 2, q = tid & 3;
        int eg = ebase + e;
        float4 v = make_float4(0.f, 0.f, 0.f, 0.f);
        if (eg < BB) v = __ldg((const float4*)(x + (size_t)eg * TT * 16) + q);
        int slot = 8 * (e / 7) + (e % 7);
        XS[(4 * q + 0) * 32 + slot] = v.x;
        XS[(4 * q + 1) * 32 + slot] = v.y;
        XS[(4 * q + 2) * 32 + slot] = v.z;
        XS[(4 * q + 3) * 32 + slot] = v.w;
    }
    __syncthreads();

    // ---------------- per-thread roles ----------------
    const int u1 = tid >> 2;          // layer1 unit 0..55 (55 = zero pad)
    const int g1 = tid & 3;           // layer1 elem group (7 elems)
    const int u2 = tid / 7;           // layer2 unit 0..31 (30,31 = pad)
    const int g2 = tid % 7;           // layer2 elem group (4 elems)

    const ulonglong2 b1v = *(const ulonglong2*)(B1 + u1);
    const ulonglong2 b2v = *(const ulonglong2*)(B2 + u2);

    float c1[7], c2[4];
#pragma unroll
    for (int j = 0; j < 7; ++j) c1[j] = 0.f;
#pragma unroll
    for (int j = 0; j < 4; ++j) c2[j] = 0.f;

    for (int t = 0; t < TT; ++t) {
        const int cur = t & 1, nxt = cur ^ 1;

        // prefetch x(t+1) into regs (hidden behind layer1)
        float4 xv = make_float4(0.f, 0.f, 0.f, 0.f);
        const bool xload = (tid < 112) && (t + 1 < TT);
        if (xload) {
            int e = tid >> 2, q = tid & 3;
            int eg = ebase + e;
            if (eg < BB)
                xv = __ldg((const float4*)(x + ((size_t)eg * TT + t + 1) * 16) + q);
        }

        // ---------------- layer 1 ----------------
        u64 aif[7], ago[7];
#pragma unroll
        for (int j = 0; j < 7; ++j) { aif[j] = b1v.x; ago[j] = b1v.y; }

        {
            const float4* wr = W1 + u1;
            const float* hr = XS + cur * (16 * 32) + 8 * g1;
#pragma unroll 2
            for (int k = 0; k < 16; ++k) {
                L1K(wr, hr);
                wr += 56; hr += 32;
            }
            hr = H1A + nxt * (56 * 32) + 8 * g1;   // h1(t-1)
#pragma unroll 2
            for (int k = 0; k < 56; ++k) {
                L1K(wr, hr);
                wr += 56; hr += 32;
            }
        }

        {
            float ho[7];
#pragma unroll
            for (int j = 0; j < 7; ++j) {
                float iv, fv, gv, ov;
                unpk(aif[j], iv, fv); unpk(ago[j], gv, ov);
                iv = sigf(iv); fv = sigf(fv);
                gv = tanhf_fast(gv); ov = sigf(ov);
                c1[j] = fv * c1[j] + iv * gv;
                ho[j] = ov * tanhf_fast(c1[j]);
            }
            float* pa = H1A + cur * (56 * 32) + u1 * 32 + 8 * g1;
            *(float4*)pa = make_float4(ho[0], ho[1], ho[2], ho[3]);
            *(float2*)(pa + 4) = make_float2(ho[4], ho[5]);
            pa[6] = ho[6];
            float* pb = H1B + cur * (56 * 28) + u1 * 28 + 7 * g1;
#pragma unroll
            for (int j = 0; j < 7; ++j) pb[j] = ho[j];
        }
        __syncthreads();   // h1(t) visible CTA-wide

        // stage x(t+1)
        if (xload) {
            int e = tid >> 2, q = tid & 3;
            int slot = 8 * (e / 7) + (e % 7);
            float* xd = XS + nxt * (16 * 32);
            xd[(4 * q + 0) * 32 + slot] = xv.x;
            xd[(4 * q + 1) * 32 + slot] = xv.y;
            xd[(4 * q + 2) * 32 + slot] = xv.z;
            xd[(4 * q + 3) * 32 + slot] = xv.w;
        }

        // ---------------- layer 2 ----------------
        u64 a2if[4], a2go[4];
#pragma unroll
        for (int j = 0; j < 4; ++j) { a2if[j] = b2v.x; a2go[j] = b2v.y; }

        {
            const float4* wr = W2 + u2;
            const float* hf = H1B + cur * (56 * 28) + 4 * g2;
#pragma unroll 2
            for (int k = 0; k < 56; ++k) {
                L2K(wr, hf);
                wr += 32; hf += 28;
            }
            hf = H2F + nxt * (30 * 28) + 4 * g2;   // h2(t-1)
#pragma unroll 2
            for (int k = 0; k < 30; ++k) {
                L2K(wr, hf);
                wr += 32; hf += 28;
            }
        }

        {
            float h2o[4];
#pragma unroll
            for (int j = 0; j < 4; ++j) {
                float iv, fv, gv, ov;
                unpk(a2if[j], iv, fv); unpk(a2go[j], gv, ov);
                iv = sigf(iv); fv = sigf(fv);
                gv = tanhf_fast(gv); ov = sigf(ov);
                c2[j] = fv * c2[j] + iv * gv;
                h2o[j] = ov * tanhf_fast(c2[j]);
            }
            if (u2 < H2)
                *(float4*)(H2F + cur * (30 * 28) + u2 * 28 + 4 * g2) =
                    make_float4(h2o[0], h2o[1], h2o[2], h2o[3]);
        }
        __syncthreads();   // h2(t), x(t+1) visible
    }

    // ---------------- final FC ----------------
    // h2(199) lives in buffer (199 & 1) = 1
    if (tid < EPC * 6) {
        const int e = tid / 6, m = tid % 6;
        const int eg = ebase + e;
        if (eg < BB) {
            const float* h2 = H2F + 1 * (30 * 28);
            float s = __ldg(bfc + m);
#pragma unroll
            for (int u = 0; u < H2; ++u)
                s += __ldg(Wfc + m * H2 + u) * h2[u * 28 + e];
            out[(size_t)eg * 6 + m] = s;
        }
    }
}

extern "C" void kernel_launch(void* const* d_in, const int* in_sizes, int n_in,
                              void* d_out, int out_size) {
    (void)in_sizes; (void)n_in; (void)out_size;
    const float* x    = (const float*)d_in[0];
    const float* Wih1 = (const float*)d_in[1];
    const float* Whh1 = (const float*)d_in[2];
    const float* bih1 = (const float*)d_in[3];
    const float* bhh1 = (const float*)d_in[4];
    const float* Wih2 = (const float*)d_in[5];
    const float* Whh2 = (const float*)d_in[6];
    const float* bih2 = (const float*)d_in[7];
    const float* bhh2 = (const float*)d_in[8];
    const float* Wfc  = (const float*)d_in[9];
    const float* bfc  = (const float*)d_in[10];
    float* out = (float*)d_out;

    static bool attr_set = false;
    if (!attr_set) {
        cudaFuncSetAttribute(lstm2_kernel,
                             cudaFuncAttributeMaxDynamicSharedMemorySize, SMEM_BYTES);
        attr_set = true;
    }
    lstm2_kernel<<<GRID, NTHR, SMEM_BYTES>>>(x, Wih1, Whh1, bih1, bhh1,
                                             Wih2, Whh2, bih2, bhh2, Wfc, bfc, out);
}

// round 7
// speedup vs baseline: 1.2637x; 1.1256x over previous
#include <cuda_runtime.h>
#include <cstdint>

typedef unsigned long long u64;

#define BB 4096
#define TT 200
#define H1 55
#define H2 30
#define NTHR 448
#define EPC 28
#define GRID 147

// ---- dynamic smem byte offsets ----
#define OFF_W1  0                    // float4[72][56]  rows: 16 x-k then 56 h1-k
#define OFF_W2  64512                // float4[86][32]  rows: 56 h1-k then 30 h2-k
#define OFF_B1  108544               // float4[56]
#define OFF_B2  109440               // float4[32]
#define OFF_XS  109952               // float[2][16][32]   x strip (8-slot groups)
#define OFF_H1A 114048               // float[2][56][32]   h1 strip, layer1 view
#define OFF_H1B 128384               // float[2][56][28]   h1 strip, layer2 view
#define OFF_H2  140928               // float[2][30][28]   h2 strip
#define SMEM_BYTES 147648

static __device__ __forceinline__ u64 pk2(float lo, float hi) {
    u64 r; asm("mov.b64 %0, {%1, %2};" : "=l"(r) : "f"(lo), "f"(hi)); return r;
}
static __device__ __forceinline__ void unpk(u64 v, float& lo, float& hi) {
    asm("mov.b64 {%0, %1}, %2;" : "=f"(lo), "=f"(hi) : "l"(v));
}
static __device__ __forceinline__ void fma2(u64& acc, u64 a, u64 b) {
    asm("fma.rn.f32x2 %0, %1, %2, %0;" : "+l"(acc) : "l"(a), "l"(b));
}
static __device__ __forceinline__ float tanhhw(float v) {
    float r; asm("tanh.approx.f32 %0, %1;" : "=f"(r) : "f"(v)); return r;
}
static __device__ __forceinline__ float sighw(float v) {
    return fmaf(0.5f, tanhhw(0.5f * v), 0.5f);
}

// layer1 k-iter: weight pair (if,go) vs 7 h values from an 8-float slot group
#define L1K(WPTR, HPTR) do { \
    const ulonglong2 wv_ = *(const ulonglong2*)(WPTR); \
    const float4 q0_ = *(const float4*)(HPTR); \
    const float4 q1_ = *(const float4*)((HPTR) + 4); \
    u64 s_; \
    s_ = pk2(q0_.x, q0_.x); fma2(aif[0], wv_.x, s_); fma2(ago[0], wv_.y, s_); \
    s_ = pk2(q0_.y, q0_.y); fma2(aif[1], wv_.x, s_); fma2(ago[1], wv_.y, s_); \
    s_ = pk2(q0_.z, q0_.z); fma2(aif[2], wv_.x, s_); fma2(ago[2], wv_.y, s_); \
    s_ = pk2(q0_.w, q0_.w); fma2(aif[3], wv_.x, s_); fma2(ago[3], wv_.y, s_); \
    s_ = pk2(q1_.x, q1_.x); fma2(aif[4], wv_.x, s_); fma2(ago[4], wv_.y, s_); \
    s_ = pk2(q1_.y, q1_.y); fma2(aif[5], wv_.x, s_); fma2(ago[5], wv_.y, s_); \
    s_ = pk2(q1_.z, q1_.z); fma2(aif[6], wv_.x, s_); fma2(ago[6], wv_.y, s_); } while (0)

// layer2 k-iter: weight pair vs 4 h values
#define L2K(WPTR, HPTR) do { \
    const ulonglong2 wv_ = *(const ulonglong2*)(WPTR); \
    const float4 hv_ = *(const float4*)(HPTR); \
    u64 s_; \
    s_ = pk2(hv_.x, hv_.x); fma2(a2if[0], wv_.x, s_); fma2(a2go[0], wv_.y, s_); \
    s_ = pk2(hv_.y, hv_.y); fma2(a2if[1], wv_.x, s_); fma2(a2go[1], wv_.y, s_); \
    s_ = pk2(hv_.z, hv_.z); fma2(a2if[2], wv_.x, s_); fma2(a2go[2], wv_.y, s_); \
    s_ = pk2(hv_.w, hv_.w); fma2(a2if[3], wv_.x, s_); fma2(a2go[3], wv_.y, s_); } while (0)

__global__ void __launch_bounds__(NTHR, 1)
lstm2_kernel(const float* __restrict__ x,
             const float* __restrict__ Wih1, const float* __restrict__ Whh1,
             const float* __restrict__ bih1, const float* __restrict__ bhh1,
             const float* __restrict__ Wih2, const float* __restrict__ Whh2,
             const float* __restrict__ bih2, const float* __restrict__ bhh2,
             const float* __restrict__ Wfc,  const float* __restrict__ bfc,
             float* __restrict__ out)
{
    extern __shared__ char sm[];
    float4* W1  = (float4*)(sm + OFF_W1);
    float4* W2  = (float4*)(sm + OFF_W2);
    float4* B1  = (float4*)(sm + OFF_B1);
    float4* B2  = (float4*)(sm + OFF_B2);
    float*  XS  = (float*)(sm + OFF_XS);
    float*  H1A = (float*)(sm + OFF_H1A);
    float*  H1B = (float*)(sm + OFF_H1B);
    float*  H2F = (float*)(sm + OFF_H2);

    const int tid = threadIdx.x;
    const int ebase = blockIdx.x * EPC;

    // ---------------- stage weights ----------------
    for (int i = tid; i < 72 * 56; i += NTHR) {
        int k = i / 56, u = i % 56;
        float4 v = make_float4(0.f, 0.f, 0.f, 0.f);
        if (u < H1) {
            if (k < 16) {
                v.x = Wih1[(0 * H1 + u) * 16 + k];
                v.y = Wih1[(1 * H1 + u) * 16 + k];
                v.z = Wih1[(2 * H1 + u) * 16 + k];
                v.w = Wih1[(3 * H1 + u) * 16 + k];
            } else if (k - 16 < H1) {
                int j = k - 16;
                v.x = Whh1[(0 * H1 + u) * H1 + j];
                v.y = Whh1[(1 * H1 + u) * H1 + j];
                v.z = Whh1[(2 * H1 + u) * H1 + j];
                v.w = Whh1[(3 * H1 + u) * H1 + j];
            }
        }
        W1[i] = v;
    }
    for (int i = tid; i < 86 * 32; i += NTHR) {
        int k = i / 32, u = i % 32;
        float4 v = make_float4(0.f, 0.f, 0.f, 0.f);
        if (u < H2) {
            if (k < 56) {
                if (k < H1) {
                    v.x = Wih2[(0 * H2 + u) * H1 + k];
                    v.y = Wih2[(1 * H2 + u) * H1 + k];
                    v.z = Wih2[(2 * H2 + u) * H1 + k];
                    v.w = Wih2[(3 * H2 + u) * H1 + k];
                }
            } else {
                int j = k - 56;
                v.x = Whh2[(0 * H2 + u) * H2 + j];
                v.y = Whh2[(1 * H2 + u) * H2 + j];
                v.z = Whh2[(2 * H2 + u) * H2 + j];
                v.w = Whh2[(3 * H2 + u) * H2 + j];
            }
        }
        W2[i] = v;
    }
    for (int u = tid; u < 56; u += NTHR) {
        float4 v = make_float4(0.f, 0.f, 0.f, 0.f);
        if (u < H1) {
            v.x = bih1[0 * H1 + u] + bhh1[0 * H1 + u];
            v.y = bih1[1 * H1 + u] + bhh1[1 * H1 + u];
            v.z = bih1[2 * H1 + u] + bhh1[2 * H1 + u];
            v.w = bih1[3 * H1 + u] + bhh1[3 * H1 + u];
        }
        B1[u] = v;
    }
    for (int u = tid; u < 32; u += NTHR) {
        float4 v = make_float4(0.f, 0.f, 0.f, 0.f);
        if (u < H2) {
            v.x = bih2[0 * H2 + u] + bhh2[0 * H2 + u];
            v.y = bih2[1 * H2 + u] + bhh2[1 * H2 + u];
            v.z = bih2[2 * H2 + u] + bhh2[2 * H2 + u];
            v.w = bih2[3 * H2 + u] + bhh2[3 * H2 + u];
        }
        B2[u] = v;
    }
    // zero all state strips (both buffers)
    for (int i = tid; i < (SMEM_BYTES - OFF_XS) / 4; i += NTHR)
        XS[i] = 0.f;
    __syncthreads();

    // stage x(t=0) into XS buf 0
    if (tid < 112) {
        int e = tid >> 2, q = tid & 3;
        int eg = ebase + e;
        float4 v = make_float4(0.f, 0.f, 0.f, 0.f);
        if (eg < BB) v = __ldg((const float4*)(x + (size_t)eg * TT * 16) + q);
        int slot = 8 * (e / 7) + (e % 7);
        XS[(4 * q + 0) * 32 + slot] = v.x;
        XS[(4 * q + 1) * 32 + slot] = v.y;
        XS[(4 * q + 2) * 32 + slot] = v.z;
        XS[(4 * q + 3) * 32 + slot] = v.w;
    }
    __syncthreads();

    // ---------------- per-thread roles ----------------
    const bool isL1 = (tid < 224);
    // L1 role (warps 0..6): unit u1 0..55, elem group g1 0..3 (7 elems each)
    const int u1 = tid >> 2;
    const int g1 = tid & 3;
    // L2 role (warps 7..13): unit u2 0..31 (30,31 pad), elem group g2 0..6 (4 elems)
    const int tl = tid - 224;
    const int u2 = isL1 ? 0 : tl / 7;
    const int g2 = isL1 ? 0 : tl % 7;

    const ulonglong2 b1v = isL1 ? *(const ulonglong2*)(B1 + u1)
                                : make_ulonglong2(0, 0);
    const ulonglong2 b2v = isL1 ? make_ulonglong2(0, 0)
                                : *(const ulonglong2*)(B2 + u2);

    float c1[7], c2[4];
#pragma unroll
    for (int j = 0; j < 7; ++j) c1[j] = 0.f;
#pragma unroll
    for (int j = 0; j < 4; ++j) c2[j] = 0.f;

    // iteration t: L1 computes h1(t) (t<TT); L2 computes h2(t-1) (t>=1)
    for (int t = 0; t < TT + 1; ++t) {
        const int cur = t & 1, nxt = cur ^ 1;

        if (isL1) {
            if (t < TT) {
                // prefetch x(t+1)
                float4 xv = make_float4(0.f, 0.f, 0.f, 0.f);
                const bool xload = (tid < 112) && (t + 1 < TT);
                if (xload) {
                    int e = tid >> 2, q = tid & 3;
                    int eg = ebase + e;
                    if (eg < BB)
                        xv = __ldg((const float4*)(x + ((size_t)eg * TT + t + 1) * 16) + q);
                }

                u64 aif[7], ago[7];
#pragma unroll
                for (int j = 0; j < 7; ++j) { aif[j] = b1v.x; ago[j] = b1v.y; }

                {
                    const float4* wr = W1 + u1;
                    const float* hr = XS + cur * (16 * 32) + 8 * g1;
#pragma unroll 2
                    for (int k = 0; k < 16; ++k) {
                        L1K(wr, hr);
                        wr += 56; hr += 32;
                    }
                    hr = H1A + nxt * (56 * 32) + 8 * g1;   // h1(t-1)
#pragma unroll 2
                    for (int k = 0; k < 56; ++k) {
                        L1K(wr, hr);
                        wr += 56; hr += 32;
                    }
                }

                float ho[7];
#pragma unroll
                for (int j = 0; j < 7; ++j) {
                    float iv, fv, gv, ov;
                    unpk(aif[j], iv, fv); unpk(ago[j], gv, ov);
                    iv = sighw(iv); fv = sighw(fv);
                    gv = tanhhw(gv); ov = sighw(ov);
                    c1[j] = fv * c1[j] + iv * gv;
                    ho[j] = ov * tanhhw(c1[j]);
                }
                float* pa = H1A + cur * (56 * 32) + u1 * 32 + 8 * g1;
                *(float4*)pa = make_float4(ho[0], ho[1], ho[2], ho[3]);
                *(float2*)(pa + 4) = make_float2(ho[4], ho[5]);
                pa[6] = ho[6];
                float* pb = H1B + cur * (56 * 28) + u1 * 28 + 7 * g1;
#pragma unroll
                for (int j = 0; j < 7; ++j) pb[j] = ho[j];

                // stage x(t+1) into XS[nxt]
                if (xload) {
                    int e = tid >> 2, q = tid & 3;
                    int slot = 8 * (e / 7) + (e % 7);
                    float* xd = XS + nxt * (16 * 32);
                    xd[(4 * q + 0) * 32 + slot] = xv.x;
                    xd[(4 * q + 1) * 32 + slot] = xv.y;
                    xd[(4 * q + 2) * 32 + slot] = xv.z;
                    xd[(4 * q + 3) * 32 + slot] = xv.w;
                }
            }
        } else {
            if (t >= 1) {
                // layer 2 for step (t-1): reads h1(t-1) buf nxt, h2(t-2) buf cur
                u64 a2if[4], a2go[4];
#pragma unroll
                for (int j = 0; j < 4; ++j) { a2if[j] = b2v.x; a2go[j] = b2v.y; }

                {
                    const float4* wr = W2 + u2;
                    const float* hf = H1B + nxt * (56 * 28) + 4 * g2;   // h1(t-1)
#pragma unroll 2
                    for (int k = 0; k < 56; ++k) {
                        L2K(wr, hf);
                        wr += 32; hf += 28;
                    }
                    hf = H2F + cur * (30 * 28) + 4 * g2;                 // h2(t-2)
#pragma unroll 2
                    for (int k = 0; k < 30; ++k) {
                        L2K(wr, hf);
                        wr += 32; hf += 28;
                    }
                }

                float h2o[4];
#pragma unroll
                for (int j = 0; j < 4; ++j) {
                    float iv, fv, gv, ov;
                    unpk(a2if[j], iv, fv); unpk(a2go[j], gv, ov);
                    iv = sighw(iv); fv = sighw(fv);
                    gv = tanhhw(gv); ov = sighw(ov);
                    c2[j] = fv * c2[j] + iv * gv;
                    h2o[j] = ov * tanhhw(c2[j]);
                }
                if (u2 < H2)
                    *(float4*)(H2F + nxt * (30 * 28) + u2 * 28 + 4 * g2) =
                        make_float4(h2o[0], h2o[1], h2o[2], h2o[3]);
            }
        }
        __syncthreads();
    }

    // ---------------- final FC ----------------
    // h2(199) lives in buffer (199 & 1) = 1
    if (tid < EPC * 6) {
        const int e = tid / 6, m = tid % 6;
        const int eg = ebase + e;
        if (eg < BB) {
            const float* h2 = H2F + 1 * (30 * 28);
            float s = __ldg(bfc + m);
#pragma unroll
            for (int u = 0; u < H2; ++u)
                s += __ldg(Wfc + m * H2 + u) * h2[u * 28 + e];
            out[(size_t)eg * 6 + m] = s;
        }
    }
}

extern "C" void kernel_launch(void* const* d_in, const int* in_sizes, int n_in,
                              void* d_out, int out_size) {
    (void)in_sizes; (void)n_in; (void)out_size;
    const float* x    = (const float*)d_in[0];
    const float* Wih1 = (const float*)d_in[1];
    const float* Whh1 = (const float*)d_in[2];
    const float* bih1 = (const float*)d_in[3];
    const float* bhh1 = (const float*)d_in[4];
    const float* Wih2 = (const float*)d_in[5];
    const float* Whh2 = (const float*)d_in[6];
    const float* bih2 = (const float*)d_in[7];
    const float* bhh2 = (const float*)d_in[8];
    const float* Wfc  = (const float*)d_in[9];
    const float* bfc  = (const float*)d_in[10];
    float* out = (float*)d_out;

    static bool attr_set = false;
    if (!attr_set) {
        cudaFuncSetAttribute(lstm2_kernel,
                             cudaFuncAttributeMaxDynamicSharedMemorySize, SMEM_BYTES);
        attr_set = true;
    }
    lstm2_kernel<<<GRID, NTHR, SMEM_BYTES>>>(x, Wih1, Whh1, bih1, bhh1,
                                             Wih2, Whh2, bih2, bhh2, Wfc, bfc, out);
}